// round 1
// baseline (speedup 1.0000x reference)
#include <cuda_runtime.h>
#include <math.h>

// Problem constants
#define BATCH 8
#define SEQ   2048
#define FEAT  1024
#define KD    512
#define VD    512
#define OUTD  1536   // FEAT + VD

// SGEMM tiling
#define BM 128
#define BN 128
#define BK 8
#define TM 8
#define TN 8

// Scratch (device globals; no allocations allowed)
__device__ float g_q[BATCH * SEQ * KD];
__device__ float g_k[BATCH * SEQ * KD];
__device__ float g_v[BATCH * SEQ * VD];
__device__ float g_logits[BATCH * SEQ * SEQ];   // reused in-place as probs

// ---------------------------------------------------------------------------
// Generic batched SGEMM: C = alpha * A (*) B + bias
//   A row-major [M,K] (lda), B: NN -> row-major [K,N] (ldb=N)
//                            NT -> row-major [N,K] (ldb=K)  (C[m,n]=sum A[m,k]*B[n,k])
//   CAUSAL_SKIP: skip tiles entirely above the diagonal (n0 > m0+BM-1)
//   CAUSAL_K:    clamp K loop to m0+BM (valid because masked probs are 0)
// ---------------------------------------------------------------------------
template<bool BT, bool CAUSAL_SKIP, bool CAUSAL_K>
__global__ __launch_bounds__(256) void sgemm_kernel(
    const float* __restrict__ A,
    const float* __restrict__ B,
    const float* __restrict__ bias,
    float* __restrict__ C,
    int M, int N, int K,
    int lda, int ldb, int ldc,
    long long sA, long long sB, long long sC,
    float alpha)
{
    const int m0 = blockIdx.y * BM;
    const int n0 = blockIdx.x * BN;
    if (CAUSAL_SKIP && n0 > m0 + (BM - 1)) return;

    A += (long long)blockIdx.z * sA;
    B += (long long)blockIdx.z * sB;
    C += (long long)blockIdx.z * sC;

    const int K_end = CAUSAL_K ? (K < m0 + BM ? K : m0 + BM) : K;

    __shared__ float As[BK][BM];
    __shared__ float Bs[BK][BN];

    const int tid = threadIdx.x;
    const int ty  = tid >> 4;   // 0..15
    const int tx  = tid & 15;   // 0..15

    // A staging: thread -> (m = tid/2, k4 = (tid&1)*4)
    const int am = tid >> 1;
    const int ak = (tid & 1) * 4;

    float acc[TM][TN];
    #pragma unroll
    for (int i = 0; i < TM; i++)
        #pragma unroll
        for (int j = 0; j < TN; j++) acc[i][j] = 0.0f;

    for (int k0 = 0; k0 < K_end; k0 += BK) {
        // stage A (transposed into As[k][m])
        float4 av = *(const float4*)&A[(long long)(m0 + am) * lda + k0 + ak];
        As[ak + 0][am] = av.x;
        As[ak + 1][am] = av.y;
        As[ak + 2][am] = av.z;
        As[ak + 3][am] = av.w;

        if (BT) {
            const int bn = tid >> 1;
            const int bk = (tid & 1) * 4;
            float4 bv = *(const float4*)&B[(long long)(n0 + bn) * ldb + k0 + bk];
            Bs[bk + 0][bn] = bv.x;
            Bs[bk + 1][bn] = bv.y;
            Bs[bk + 2][bn] = bv.z;
            Bs[bk + 3][bn] = bv.w;
        } else {
            const int bk = tid >> 5;          // 0..7
            const int bn = (tid & 31) * 4;    // 0..124
            float4 bv = *(const float4*)&B[(long long)(k0 + bk) * ldb + n0 + bn];
            *(float4*)&Bs[bk][bn] = bv;
        }
        __syncthreads();

        #pragma unroll
        for (int kk = 0; kk < BK; kk++) {
            float a[TM], b[TN];
            #pragma unroll
            for (int i = 0; i < TM; i++) a[i] = As[kk][ty * TM + i];
            #pragma unroll
            for (int j = 0; j < TN; j++) b[j] = Bs[kk][tx * TN + j];
            #pragma unroll
            for (int i = 0; i < TM; i++)
                #pragma unroll
                for (int j = 0; j < TN; j++)
                    acc[i][j] = fmaf(a[i], b[j], acc[i][j]);
        }
        __syncthreads();
    }

    // epilogue
    #pragma unroll
    for (int i = 0; i < TM; i++) {
        const int m = m0 + ty * TM + i;
        #pragma unroll
        for (int j = 0; j < TN; j += 4) {
            const int n = n0 + tx * TN + j;
            float4 v;
            v.x = acc[i][j + 0] * alpha;
            v.y = acc[i][j + 1] * alpha;
            v.z = acc[i][j + 2] * alpha;
            v.w = acc[i][j + 3] * alpha;
            if (bias) {
                v.x += bias[n + 0];
                v.y += bias[n + 1];
                v.z += bias[n + 2];
                v.w += bias[n + 3];
            }
            *(float4*)&C[(long long)m * ldc + n] = v;
        }
    }
}

// ---------------------------------------------------------------------------
// Row softmax, in place on g_logits. One block per (b, q) row.
// Valid region [0, q]; writes zeros to [q+1, SEQ) so PV can be a dense GEMM.
// ---------------------------------------------------------------------------
__global__ __launch_bounds__(256) void softmax_kernel(float* __restrict__ logits)
{
    const long long row = blockIdx.x;               // 0 .. BATCH*SEQ-1
    const int q = (int)(row % SEQ);
    float* p = logits + row * SEQ;
    const int len = q + 1;
    const int tid = threadIdx.x;

    __shared__ float red[256];

    float mx = -INFINITY;
    for (int i = tid; i < len; i += 256) mx = fmaxf(mx, p[i]);
    red[tid] = mx;
    __syncthreads();
    for (int s = 128; s > 0; s >>= 1) {
        if (tid < s) red[tid] = fmaxf(red[tid], red[tid + s]);
        __syncthreads();
    }
    mx = red[0];
    __syncthreads();

    float sum = 0.0f;
    for (int i = tid; i < len; i += 256) {
        float e = expf(p[i] - mx);
        p[i] = e;
        sum += e;
    }
    red[tid] = sum;
    __syncthreads();
    for (int s = 128; s > 0; s >>= 1) {
        if (tid < s) red[tid] += red[tid + s];
        __syncthreads();
    }
    const float inv = 1.0f / red[0];
    __syncthreads();

    for (int i = tid; i < len; i += 256) p[i] *= inv;
    for (int i = len + tid; i < SEQ; i += 256) p[i] = 0.0f;
}

// ---------------------------------------------------------------------------
// Copy x into out[..., 0:FEAT] (float4 vectorized)
// ---------------------------------------------------------------------------
__global__ __launch_bounds__(256) void copy_x_kernel(const float4* __restrict__ x,
                                                     float4* __restrict__ out)
{
    const long long i = (long long)blockIdx.x * blockDim.x + threadIdx.x;
    const long long total = (long long)BATCH * SEQ * (FEAT / 4);
    if (i >= total) return;
    const long long row = i / (FEAT / 4);
    const int col = (int)(i % (FEAT / 4));
    out[row * (OUTD / 4) + col] = x[i];
}

// ---------------------------------------------------------------------------
extern "C" void kernel_launch(void* const* d_in, const int* in_sizes, int n_in,
                              void* d_out, int out_size)
{
    const float* x  = (const float*)d_in[0];
    const float* Wq = (const float*)d_in[1];
    const float* bq = (const float*)d_in[2];
    const float* Wk = (const float*)d_in[3];
    const float* bk = (const float*)d_in[4];
    const float* Wv = (const float*)d_in[5];
    const float* bv = (const float*)d_in[6];
    float* out = (float*)d_out;

    float *q, *k, *v, *logits;
    cudaGetSymbolAddress((void**)&q,      g_q);
    cudaGetSymbolAddress((void**)&k,      g_k);
    cudaGetSymbolAddress((void**)&v,      g_v);
    cudaGetSymbolAddress((void**)&logits, g_logits);

    const int M = BATCH * SEQ;          // 16384
    const float scale = 0.044194173824159216f;  // 1/sqrt(512)

    // QKV projections: [16384,1024] x [1024,512] + bias
    {
        dim3 grid(KD / BN, M / BM, 1);
        sgemm_kernel<false, false, false><<<grid, 256>>>(
            x, Wq, bq, q, M, KD, FEAT, FEAT, KD, KD, 0, 0, 0, 1.0f);
        sgemm_kernel<false, false, false><<<grid, 256>>>(
            x, Wk, bk, k, M, KD, FEAT, FEAT, KD, KD, 0, 0, 0, 1.0f);
        sgemm_kernel<false, false, false><<<grid, 256>>>(
            x, Wv, bv, v, M, VD, FEAT, FEAT, VD, VD, 0, 0, 0, 1.0f);
    }

    // logits = scale * Q @ K^T  (NT, skip upper-triangle tiles), batched over 8
    {
        dim3 grid(SEQ / BN, SEQ / BM, BATCH);
        sgemm_kernel<true, true, false><<<grid, 256>>>(
            q, k, nullptr, logits, SEQ, SEQ, KD, KD, KD, SEQ,
            (long long)SEQ * KD, (long long)SEQ * KD, (long long)SEQ * SEQ, scale);
    }

    // softmax rows (in place, zero masked tail)
    softmax_kernel<<<BATCH * SEQ, 256>>>(logits);

    // read = P @ V, written directly into out[..., FEAT:], K-loop causally clamped
    {
        dim3 grid(VD / BN, SEQ / BM, BATCH);
        sgemm_kernel<false, false, true><<<grid, 256>>>(
            logits, v, nullptr, out + FEAT, SEQ, VD, SEQ, SEQ, VD, OUTD,
            (long long)SEQ * SEQ, (long long)SEQ * KD, (long long)SEQ * OUTD, 1.0f);
    }

    // out[..., 0:FEAT] = x
    {
        const long long total = (long long)BATCH * SEQ * (FEAT / 4);
        const int grid = (int)((total + 255) / 256);
        copy_x_kernel<<<grid, 256>>>((const float4*)x, (float4*)out);
    }
}

// round 2
// speedup vs baseline: 2.9622x; 2.9622x over previous
#include <cuda_runtime.h>
#include <math.h>
#include <stdint.h>

// Problem constants
#define BATCH 8
#define SEQ   2048
#define FEAT  1024
#define KD    512
#define VD    512
#define OUTD  1536   // FEAT + VD

// Scratch (device globals; no allocations allowed)
__device__ float g_q[BATCH * SEQ * KD];
__device__ float g_k[BATCH * SEQ * KD];
__device__ float g_v[BATCH * SEQ * VD];
__device__ float g_logits[BATCH * SEQ * SEQ];   // reused in-place as probs

__device__ __forceinline__ uint32_t f2tf32(float x) {
    uint32_t u;
    asm volatile("cvt.rna.tf32.f32 %0, %1;" : "=r"(u) : "f"(x));
    return u;
}

// ---------------------------------------------------------------------------
// Tensor-core GEMM (mma.sync m16n8k8 tf32): C = alpha * A (*) B + bias
//   CTA tile 128x128, BK=32. 8 warps: 2 (M) x 4 (N), warp tile 64x32.
//   A row-major [M,K]; BT=false: B row-major [K,N]; BT=true: B row-major [N,K]
//   CAUSAL_SKIP: skip tiles strictly above the diagonal
//   CAUSAL_K:    clamp K loop to m0+128 (masked probs are exact zeros)
// ---------------------------------------------------------------------------
template<bool BT, bool CAUSAL_SKIP, bool CAUSAL_K>
__global__ __launch_bounds__(256) void mma_gemm(
    const float* __restrict__ A,
    const float* __restrict__ B,
    const float* __restrict__ bias,
    float* __restrict__ C,
    int M, int N, int K,
    int lda, int ldb, int ldc,
    long long sA, long long sB, long long sC,
    float alpha)
{
    const int m0 = blockIdx.y * 128;
    const int n0 = blockIdx.x * 128;
    if (CAUSAL_SKIP && n0 > m0 + 127) return;

    A += (long long)blockIdx.z * sA;
    B += (long long)blockIdx.z * sB;
    C += (long long)blockIdx.z * sC;

    const int K_end = CAUSAL_K ? (K < m0 + 128 ? K : m0 + 128) : K;

    // A: row-major [128][32], stride 36 -> conflict-free frag loads
    __shared__ uint32_t As[128 * 36];
    // B: BT -> n-major [128][32] stride 36; NN -> k-major [32][128] stride 132
    constexpr int BS_WORDS = BT ? (128 * 36) : (32 * 132);
    __shared__ uint32_t Bs[BS_WORDS];

    const int tid  = threadIdx.x;
    const int lane = tid & 31;
    const int w    = tid >> 5;
    const int wm   = w & 1;       // 0..1
    const int wn   = w >> 1;      // 0..3
    const int l4   = lane >> 2;   // 0..7
    const int lm   = lane & 3;    // 0..3

    float acc[4][4][4];
    #pragma unroll
    for (int i = 0; i < 4; i++)
        #pragma unroll
        for (int j = 0; j < 4; j++)
            #pragma unroll
            for (int r = 0; r < 4; r++) acc[i][j][r] = 0.0f;

    for (int k0 = 0; k0 < K_end; k0 += 32) {
        // ---- stage A (tf32-converted, uint4 stores) ----
        #pragma unroll
        for (int i = 0; i < 4; i++) {
            const int idx = tid + i * 256;
            const int r   = idx >> 3;
            const int c4  = (idx & 7) << 2;
            float4 v = *(const float4*)&A[(long long)(m0 + r) * lda + k0 + c4];
            uint4 u = make_uint4(f2tf32(v.x), f2tf32(v.y), f2tf32(v.z), f2tf32(v.w));
            *(uint4*)&As[r * 36 + c4] = u;
        }
        // ---- stage B ----
        if (BT) {
            #pragma unroll
            for (int i = 0; i < 4; i++) {
                const int idx = tid + i * 256;
                const int r   = idx >> 3;
                const int c4  = (idx & 7) << 2;
                float4 v = *(const float4*)&B[(long long)(n0 + r) * ldb + k0 + c4];
                uint4 u = make_uint4(f2tf32(v.x), f2tf32(v.y), f2tf32(v.z), f2tf32(v.w));
                *(uint4*)&Bs[r * 36 + c4] = u;
            }
        } else {
            #pragma unroll
            for (int i = 0; i < 4; i++) {
                const int idx = tid + i * 256;
                const int kk  = idx >> 5;
                const int n4  = (idx & 31) << 2;
                float4 v = *(const float4*)&B[(long long)(k0 + kk) * ldb + n0 + n4];
                uint4 u = make_uint4(f2tf32(v.x), f2tf32(v.y), f2tf32(v.z), f2tf32(v.w));
                *(uint4*)&Bs[kk * 132 + n4] = u;
            }
        }
        __syncthreads();

        // ---- 4 mma k-steps of 8 ----
        #pragma unroll
        for (int ks = 0; ks < 4; ks++) {
            const int kk = ks * 8;
            uint32_t a[4][4];
            uint32_t b[4][2];
            #pragma unroll
            for (int tm = 0; tm < 4; tm++) {
                const uint32_t* p = &As[(wm * 64 + tm * 16 + l4) * 36 + kk + lm];
                a[tm][0] = p[0];
                a[tm][1] = p[8 * 36];
                a[tm][2] = p[4];
                a[tm][3] = p[8 * 36 + 4];
            }
            #pragma unroll
            for (int tn = 0; tn < 4; tn++) {
                if (BT) {
                    const uint32_t* p = &Bs[(wn * 32 + tn * 8 + l4) * 36 + kk + lm];
                    b[tn][0] = p[0];
                    b[tn][1] = p[4];
                } else {
                    const uint32_t* p = &Bs[(kk + lm) * 132 + wn * 32 + tn * 8 + l4];
                    b[tn][0] = p[0];
                    b[tn][1] = p[4 * 132];
                }
            }
            #pragma unroll
            for (int tm = 0; tm < 4; tm++)
                #pragma unroll
                for (int tn = 0; tn < 4; tn++) {
                    asm volatile(
                        "mma.sync.aligned.m16n8k8.row.col.f32.tf32.tf32.f32 "
                        "{%0,%1,%2,%3}, {%4,%5,%6,%7}, {%8,%9}, {%0,%1,%2,%3};\n"
                        : "+f"(acc[tm][tn][0]), "+f"(acc[tm][tn][1]),
                          "+f"(acc[tm][tn][2]), "+f"(acc[tm][tn][3])
                        : "r"(a[tm][0]), "r"(a[tm][1]), "r"(a[tm][2]), "r"(a[tm][3]),
                          "r"(b[tn][0]), "r"(b[tn][1]));
                }
        }
        __syncthreads();
    }

    // ---- epilogue ----
    #pragma unroll
    for (int tm = 0; tm < 4; tm++) {
        const int row = m0 + wm * 64 + tm * 16 + l4;
        #pragma unroll
        for (int tn = 0; tn < 4; tn++) {
            const int col = n0 + wn * 32 + tn * 8 + (lm << 1);
            float bx = 0.0f, by = 0.0f;
            if (bias) { bx = bias[col]; by = bias[col + 1]; }
            float2 v0, v1;
            v0.x = acc[tm][tn][0] * alpha + bx;
            v0.y = acc[tm][tn][1] * alpha + by;
            v1.x = acc[tm][tn][2] * alpha + bx;
            v1.y = acc[tm][tn][3] * alpha + by;
            *(float2*)&C[(long long)row * ldc + col]       = v0;
            *(float2*)&C[(long long)(row + 8) * ldc + col] = v1;
        }
    }
}

// ---------------------------------------------------------------------------
// Row softmax, in place on g_logits. One block per (b, q) row.
// Valid region [0, q]; writes zeros to [q+1, SEQ) so PV can be a dense GEMM.
// ---------------------------------------------------------------------------
__global__ __launch_bounds__(256) void softmax_kernel(float* __restrict__ logits)
{
    const long long row = blockIdx.x;               // 0 .. BATCH*SEQ-1
    const int q = (int)(row % SEQ);
    float* p = logits + row * SEQ;
    const int len = q + 1;
    const int tid = threadIdx.x;

    __shared__ float red[256];

    float mx = -INFINITY;
    for (int i = tid; i < len; i += 256) mx = fmaxf(mx, p[i]);
    red[tid] = mx;
    __syncthreads();
    for (int s = 128; s > 0; s >>= 1) {
        if (tid < s) red[tid] = fmaxf(red[tid], red[tid + s]);
        __syncthreads();
    }
    mx = red[0];
    __syncthreads();

    float sum = 0.0f;
    for (int i = tid; i < len; i += 256) {
        float e = expf(p[i] - mx);
        p[i] = e;
        sum += e;
    }
    red[tid] = sum;
    __syncthreads();
    for (int s = 128; s > 0; s >>= 1) {
        if (tid < s) red[tid] += red[tid + s];
        __syncthreads();
    }
    const float inv = 1.0f / red[0];
    __syncthreads();

    for (int i = tid; i < len; i += 256) p[i] *= inv;
    for (int i = len + tid; i < SEQ; i += 256) p[i] = 0.0f;
}

// ---------------------------------------------------------------------------
// Copy x into out[..., 0:FEAT] (float4 vectorized)
// ---------------------------------------------------------------------------
__global__ __launch_bounds__(256) void copy_x_kernel(const float4* __restrict__ x,
                                                     float4* __restrict__ out)
{
    const long long i = (long long)blockIdx.x * blockDim.x + threadIdx.x;
    const long long total = (long long)BATCH * SEQ * (FEAT / 4);
    if (i >= total) return;
    const long long row = i / (FEAT / 4);
    const int col = (int)(i % (FEAT / 4));
    out[row * (OUTD / 4) + col] = x[i];
}

// ---------------------------------------------------------------------------
extern "C" void kernel_launch(void* const* d_in, const int* in_sizes, int n_in,
                              void* d_out, int out_size)
{
    const float* x  = (const float*)d_in[0];
    const float* Wq = (const float*)d_in[1];
    const float* bq = (const float*)d_in[2];
    const float* Wk = (const float*)d_in[3];
    const float* bk = (const float*)d_in[4];
    const float* Wv = (const float*)d_in[5];
    const float* bv = (const float*)d_in[6];
    float* out = (float*)d_out;

    float *q, *k, *v, *logits;
    cudaGetSymbolAddress((void**)&q,      g_q);
    cudaGetSymbolAddress((void**)&k,      g_k);
    cudaGetSymbolAddress((void**)&v,      g_v);
    cudaGetSymbolAddress((void**)&logits, g_logits);

    const int M = BATCH * SEQ;          // 16384
    const float scale = 0.044194173824159216f;  // 1/sqrt(512)

    // QKV projections: [16384,1024] x [1024,512] + bias
    {
        dim3 grid(KD / 128, M / 128, 1);
        mma_gemm<false, false, false><<<grid, 256>>>(
            x, Wq, bq, q, M, KD, FEAT, FEAT, KD, KD, 0, 0, 0, 1.0f);
        mma_gemm<false, false, false><<<grid, 256>>>(
            x, Wk, bk, k, M, KD, FEAT, FEAT, KD, KD, 0, 0, 0, 1.0f);
        mma_gemm<false, false, false><<<grid, 256>>>(
            x, Wv, bv, v, M, VD, FEAT, FEAT, VD, VD, 0, 0, 0, 1.0f);
    }

    // logits = scale * Q @ K^T  (NT, skip upper-triangle tiles), batched over 8
    {
        dim3 grid(SEQ / 128, SEQ / 128, BATCH);
        mma_gemm<true, true, false><<<grid, 256>>>(
            q, k, nullptr, logits, SEQ, SEQ, KD, KD, KD, SEQ,
            (long long)SEQ * KD, (long long)SEQ * KD, (long long)SEQ * SEQ, scale);
    }

    // softmax rows (in place, zero masked tail)
    softmax_kernel<<<BATCH * SEQ, 256>>>(logits);

    // read = P @ V, written directly into out[..., FEAT:], K-loop causally clamped
    {
        dim3 grid(VD / 128, SEQ / 128, BATCH);
        mma_gemm<false, false, true><<<grid, 256>>>(
            logits, v, nullptr, out + FEAT, SEQ, VD, SEQ, SEQ, VD, OUTD,
            (long long)SEQ * SEQ, (long long)SEQ * KD, (long long)SEQ * OUTD, 1.0f);
    }

    // out[..., 0:FEAT] = x
    {
        const long long total = (long long)BATCH * SEQ * (FEAT / 4);
        const int grid = (int)((total + 255) / 256);
        copy_x_kernel<<<grid, 256>>>((const float4*)x, (float4*)out);
    }
}

// round 3
// speedup vs baseline: 3.0662x; 1.0351x over previous
#include <cuda_runtime.h>
#include <math.h>
#include <stdint.h>

// Problem constants
#define BATCH 8
#define SEQ   2048
#define FEAT  1024
#define KD    512
#define VD    512
#define OUTD  1536   // FEAT + VD

// Scratch (device globals; no allocations allowed)
__device__ float g_q[BATCH * SEQ * KD];
__device__ float g_k[BATCH * SEQ * KD];
__device__ float g_v[BATCH * SEQ * VD];
__device__ float g_logits[BATCH * SEQ * SEQ];   // reused in-place as probs (unnormalized)
__device__ float g_rsum[BATCH * SEQ];           // 1/rowsum for PV epilogue

#define A_STRIDE  40   // words; 160B row pitch (mult of 16B), conflict-free frags
#define BT_STRIDE 40
#define BN_STRIDE 136  // words; 544B row pitch (mult of 16B), conflict-free frags

__device__ __forceinline__ void cp16(uint32_t* dst, const void* src) {
    uint32_t a = (uint32_t)__cvta_generic_to_shared(dst);
    asm volatile("cp.async.cg.shared.global [%0], [%1], 16;\n" :: "r"(a), "l"(src));
}
__device__ __forceinline__ void cp_commit() {
    asm volatile("cp.async.commit_group;\n" ::: "memory");
}
__device__ __forceinline__ void cp_wait1() {
    asm volatile("cp.async.wait_group 1;\n" ::: "memory");
}

// ---------------------------------------------------------------------------
// Tensor-core GEMM (mma m16n8k8 tf32, raw fp32 bits = RZ truncation):
//   C = alpha * rowscale[m] * (A (*) B) + bias
//   CTA tile 128x128, BK=32, 2-stage cp.async pipeline.
//   8 warps: 2 (M) x 4 (N), warp tile 64x32.
//   A row-major [M,K]; BT=false: B row-major [K,N]; BT=true: B row-major [N,K]
//   CAUSAL_SKIP: skip tiles strictly above the diagonal
//   CAUSAL_K:    clamp K loop to m0+128 (probs in band are zeroed by softmax)
// ---------------------------------------------------------------------------
template<bool BT, bool CAUSAL_SKIP, bool CAUSAL_K>
__global__ __launch_bounds__(256) void mma_gemm(
    const float* __restrict__ A,
    const float* __restrict__ B,
    const float* __restrict__ bias,
    const float* __restrict__ rowscale,
    float* __restrict__ C,
    int M, int N, int K,
    int lda, int ldb, int ldc,
    long long sA, long long sB, long long sC,
    float alpha)
{
    const int m0 = blockIdx.y * 128;
    const int n0 = blockIdx.x * 128;
    if (CAUSAL_SKIP && n0 > m0 + 127) return;

    A += (long long)blockIdx.z * sA;
    B += (long long)blockIdx.z * sB;
    C += (long long)blockIdx.z * sC;
    if (rowscale) rowscale += (long long)blockIdx.z * SEQ;

    const int K_end = CAUSAL_K ? (K < m0 + 128 ? K : m0 + 128) : K;
    const int n_iter = K_end >> 5;

    extern __shared__ uint32_t smem[];
    constexpr int A_WORDS = 128 * A_STRIDE;
    constexpr int B_WORDS = BT ? (128 * BT_STRIDE) : (32 * BN_STRIDE);
    uint32_t* As[2] = { smem,               smem + A_WORDS };
    uint32_t* Bs[2] = { smem + 2 * A_WORDS, smem + 2 * A_WORDS + B_WORDS };

    const int tid  = threadIdx.x;
    const int lane = tid & 31;
    const int w    = tid >> 5;
    const int wm   = w & 1;       // 0..1
    const int wn   = w >> 1;      // 0..3
    const int l4   = lane >> 2;   // 0..7
    const int lm   = lane & 3;    // 0..3

    // per-thread staging coordinates
    const int ar  = tid >> 1;            // A/B-NT: covers 128 rows with 2 chunks/row
    const int ac4 = (tid & 1) * 4;       // then +8 col offset on second pass? no: 4 chunks below
    (void)ar; (void)ac4;

    auto load_tile = [&](int k0, int s) {
        // A: 128x32 floats = 1024 float4 chunks; 256 threads x 4
        #pragma unroll
        for (int i = 0; i < 4; i++) {
            const int idx = tid + i * 256;
            const int r   = idx >> 3;
            const int c4  = (idx & 7) << 2;
            cp16(&As[s][r * A_STRIDE + c4],
                 &A[(long long)(m0 + r) * lda + k0 + c4]);
        }
        if (BT) {
            #pragma unroll
            for (int i = 0; i < 4; i++) {
                const int idx = tid + i * 256;
                const int r   = idx >> 3;
                const int c4  = (idx & 7) << 2;
                cp16(&Bs[s][r * BT_STRIDE + c4],
                     &B[(long long)(n0 + r) * ldb + k0 + c4]);
            }
        } else {
            #pragma unroll
            for (int i = 0; i < 4; i++) {
                const int idx = tid + i * 256;
                const int kk  = idx >> 5;
                const int n4  = (idx & 31) << 2;
                cp16(&Bs[s][kk * BN_STRIDE + n4],
                     &B[(long long)(k0 + kk) * ldb + n0 + n4]);
            }
        }
    };

    float acc[4][4][4];
    #pragma unroll
    for (int i = 0; i < 4; i++)
        #pragma unroll
        for (int j = 0; j < 4; j++)
            #pragma unroll
            for (int r = 0; r < 4; r++) acc[i][j][r] = 0.0f;

    load_tile(0, 0);
    cp_commit();

    for (int it = 0; it < n_iter; it++) {
        const int s = it & 1;
        if (it + 1 < n_iter) load_tile((it + 1) << 5, s ^ 1);
        cp_commit();          // always one group per iter (possibly empty)
        cp_wait1();           // stage s complete
        __syncthreads();

        #pragma unroll
        for (int ks = 0; ks < 4; ks++) {
            const int kk = ks * 8;
            uint32_t a[4][4];
            uint32_t b[4][2];
            #pragma unroll
            for (int tm = 0; tm < 4; tm++) {
                const uint32_t* p = &As[s][(wm * 64 + tm * 16 + l4) * A_STRIDE + kk + lm];
                a[tm][0] = p[0];
                a[tm][1] = p[8 * A_STRIDE];
                a[tm][2] = p[4];
                a[tm][3] = p[8 * A_STRIDE + 4];
            }
            #pragma unroll
            for (int tn = 0; tn < 4; tn++) {
                if (BT) {
                    const uint32_t* p = &Bs[s][(wn * 32 + tn * 8 + l4) * BT_STRIDE + kk + lm];
                    b[tn][0] = p[0];
                    b[tn][1] = p[4];
                } else {
                    const uint32_t* p = &Bs[s][(kk + lm) * BN_STRIDE + wn * 32 + tn * 8 + l4];
                    b[tn][0] = p[0];
                    b[tn][1] = p[4 * BN_STRIDE];
                }
            }
            #pragma unroll
            for (int tm = 0; tm < 4; tm++)
                #pragma unroll
                for (int tn = 0; tn < 4; tn++) {
                    asm volatile(
                        "mma.sync.aligned.m16n8k8.row.col.f32.tf32.tf32.f32 "
                        "{%0,%1,%2,%3}, {%4,%5,%6,%7}, {%8,%9}, {%0,%1,%2,%3};\n"
                        : "+f"(acc[tm][tn][0]), "+f"(acc[tm][tn][1]),
                          "+f"(acc[tm][tn][2]), "+f"(acc[tm][tn][3])
                        : "r"(a[tm][0]), "r"(a[tm][1]), "r"(a[tm][2]), "r"(a[tm][3]),
                          "r"(b[tn][0]), "r"(b[tn][1]));
                }
        }
        __syncthreads();
    }

    // ---- epilogue ----
    #pragma unroll
    for (int tm = 0; tm < 4; tm++) {
        const int row  = m0 + wm * 64 + tm * 16 + l4;
        float f0 = alpha, f1 = alpha;
        if (rowscale) { f0 = alpha * rowscale[row]; f1 = alpha * rowscale[row + 8]; }
        #pragma unroll
        for (int tn = 0; tn < 4; tn++) {
            const int col = n0 + wn * 32 + tn * 8 + (lm << 1);
            float bx = 0.0f, by = 0.0f;
            if (bias) { bx = bias[col]; by = bias[col + 1]; }
            float2 v0, v1;
            v0.x = acc[tm][tn][0] * f0 + bx;
            v0.y = acc[tm][tn][1] * f0 + by;
            v1.x = acc[tm][tn][2] * f1 + bx;
            v1.y = acc[tm][tn][3] * f1 + by;
            *(float2*)&C[(long long)row * ldc + col]       = v0;
            *(float2*)&C[(long long)(row + 8) * ldc + col] = v1;
        }
    }
}

// ---------------------------------------------------------------------------
// Row softmax (unnormalized): p[i] = exp(p[i]-max); g_rsum[row] = 1/sum.
// Zeros only the diagonal band tail [q+1, ceil128(q+1)) that PV's clamped
// K-loop can touch. Normalization happens in the PV epilogue via rowscale.
// ---------------------------------------------------------------------------
__global__ __launch_bounds__(256) void softmax_kernel(float* __restrict__ logits,
                                                      float* __restrict__ rsum)
{
    const long long row = blockIdx.x;               // 0 .. BATCH*SEQ-1
    const int q = (int)(row % SEQ);
    float* p = logits + row * SEQ;
    const int len = q + 1;
    const int band = ((q >> 7) + 1) << 7;           // PV K_end for this row
    const int tid = threadIdx.x;

    __shared__ float red[256];

    float mx = -INFINITY;
    for (int i = tid; i < len; i += 256) mx = fmaxf(mx, p[i]);
    red[tid] = mx;
    __syncthreads();
    for (int s = 128; s > 0; s >>= 1) {
        if (tid < s) red[tid] = fmaxf(red[tid], red[tid + s]);
        __syncthreads();
    }
    mx = red[0];
    __syncthreads();

    float sum = 0.0f;
    for (int i = tid; i < len; i += 256) {
        float e = expf(p[i] - mx);
        p[i] = e;
        sum += e;
    }
    red[tid] = sum;
    __syncthreads();
    for (int s = 128; s > 0; s >>= 1) {
        if (tid < s) red[tid] += red[tid + s];
        __syncthreads();
    }
    if (tid == 0) rsum[row] = 1.0f / red[0];

    for (int i = len + tid; i < band; i += 256) p[i] = 0.0f;
}

// ---------------------------------------------------------------------------
// Copy x into out[..., 0:FEAT] (float4 vectorized)
// ---------------------------------------------------------------------------
__global__ __launch_bounds__(256) void copy_x_kernel(const float4* __restrict__ x,
                                                     float4* __restrict__ out)
{
    const long long i = (long long)blockIdx.x * blockDim.x + threadIdx.x;
    const long long total = (long long)BATCH * SEQ * (FEAT / 4);
    if (i >= total) return;
    const long long row = i / (FEAT / 4);
    const int col = (int)(i % (FEAT / 4));
    out[row * (OUTD / 4) + col] = x[i];
}

// ---------------------------------------------------------------------------
extern "C" void kernel_launch(void* const* d_in, const int* in_sizes, int n_in,
                              void* d_out, int out_size)
{
    const float* x  = (const float*)d_in[0];
    const float* Wq = (const float*)d_in[1];
    const float* bq = (const float*)d_in[2];
    const float* Wk = (const float*)d_in[3];
    const float* bk = (const float*)d_in[4];
    const float* Wv = (const float*)d_in[5];
    const float* bv = (const float*)d_in[6];
    float* out = (float*)d_out;

    float *q, *k, *v, *logits, *rsum;
    cudaGetSymbolAddress((void**)&q,      g_q);
    cudaGetSymbolAddress((void**)&k,      g_k);
    cudaGetSymbolAddress((void**)&v,      g_v);
    cudaGetSymbolAddress((void**)&logits, g_logits);
    cudaGetSymbolAddress((void**)&rsum,   g_rsum);

    const int M = BATCH * SEQ;          // 16384
    const float scale = 0.044194173824159216f;  // 1/sqrt(512)

    // dynamic smem sizes
    constexpr int SM_NN = (2 * 128 * A_STRIDE + 2 * 32 * BN_STRIDE) * 4;   // 75776 B
    constexpr int SM_NT = (2 * 128 * A_STRIDE + 2 * 128 * BT_STRIDE) * 4;  // 81920 B
    cudaFuncSetAttribute(mma_gemm<false, false, false>,
                         cudaFuncAttributeMaxDynamicSharedMemorySize, SM_NN);
    cudaFuncSetAttribute(mma_gemm<true, true, false>,
                         cudaFuncAttributeMaxDynamicSharedMemorySize, SM_NT);
    cudaFuncSetAttribute(mma_gemm<false, false, true>,
                         cudaFuncAttributeMaxDynamicSharedMemorySize, SM_NN);

    // QKV projections: [16384,1024] x [1024,512] + bias
    {
        dim3 grid(KD / 128, M / 128, 1);
        mma_gemm<false, false, false><<<grid, 256, SM_NN>>>(
            x, Wq, bq, nullptr, q, M, KD, FEAT, FEAT, KD, KD, 0, 0, 0, 1.0f);
        mma_gemm<false, false, false><<<grid, 256, SM_NN>>>(
            x, Wk, bk, nullptr, k, M, KD, FEAT, FEAT, KD, KD, 0, 0, 0, 1.0f);
        mma_gemm<false, false, false><<<grid, 256, SM_NN>>>(
            x, Wv, bv, nullptr, v, M, VD, FEAT, FEAT, VD, VD, 0, 0, 0, 1.0f);
    }

    // logits = scale * Q @ K^T  (NT, skip upper-triangle tiles), batched over 8
    {
        dim3 grid(SEQ / 128, SEQ / 128, BATCH);
        mma_gemm<true, true, false><<<grid, 256, SM_NT>>>(
            q, k, nullptr, nullptr, logits, SEQ, SEQ, KD, KD, KD, SEQ,
            (long long)SEQ * KD, (long long)SEQ * KD, (long long)SEQ * SEQ, scale);
    }

    // softmax rows (unnormalized, band-zeroed; 1/sum saved for PV)
    softmax_kernel<<<BATCH * SEQ, 256>>>(logits, rsum);

    // read = (P @ V) * rowscale, written into out[..., FEAT:], K clamped to band
    {
        dim3 grid(VD / 128, SEQ / 128, BATCH);
        mma_gemm<false, false, true><<<grid, 256, SM_NN>>>(
            logits, v, nullptr, rsum, out + FEAT, SEQ, VD, SEQ, SEQ, VD, OUTD,
            (long long)SEQ * SEQ, (long long)SEQ * KD, (long long)SEQ * OUTD, 1.0f);
    }

    // out[..., 0:FEAT] = x
    {
        const long long total = (long long)BATCH * SEQ * (FEAT / 4);
        const int grid = (int)((total + 255) / 256);
        copy_x_kernel<<<grid, 256>>>((const float4*)x, (float4*)out);
    }
}

// round 4
// speedup vs baseline: 3.6294x; 1.1837x over previous
#include <cuda_runtime.h>
#include <math.h>
#include <stdint.h>

// Problem constants
#define BATCH 8
#define SEQ   2048
#define FEAT  1024
#define KD    512
#define VD    512
#define OUTD  1536   // FEAT + VD

// Scratch (device globals; no allocations allowed)
__device__ float g_q[BATCH * SEQ * KD];
__device__ float g_k[BATCH * SEQ * KD];
__device__ float g_v[BATCH * SEQ * VD];
__device__ float g_logits[BATCH * SEQ * SEQ];   // probs, unnormalized
__device__ float g_rsum[BATCH * SEQ];           // 1/rowsum for PV epilogue

#define A_STRIDE  40   // words; conflict-free frag loads, 16B-multiple pitch
#define BT_STRIDE 40
#define BN_STRIDE 136

__device__ __forceinline__ void cp16(uint32_t* dst, const void* src) {
    uint32_t a = (uint32_t)__cvta_generic_to_shared(dst);
    asm volatile("cp.async.cg.shared.global [%0], [%1], 16;\n" :: "r"(a), "l"(src));
}
__device__ __forceinline__ void cp_commit() {
    asm volatile("cp.async.commit_group;\n" ::: "memory");
}
__device__ __forceinline__ void cp_wait1() {
    asm volatile("cp.async.wait_group 1;\n" ::: "memory");
}

// ---------------------------------------------------------------------------
// Tensor-core GEMM (mma m16n8k8 tf32, raw fp32 bits = RZ truncation)
// CTA tile 128x128, BK=32, 2-stage cp.async pipeline, 2 CTAs/SM.
// MODE 0: fused QKV projection. NN. blockIdx.z in {0,1,2} selects (B,bias,C).
//         A = x [16384,1024], B = W [1024,512], C = q/k/v [16384,512].
// MODE 1: QK^T. NT, causal tile skip. blockIdx.z = batch.
// MODE 2: PV.  NN, causal K clamp, rowscale epilogue. blockIdx.z = batch.
// ---------------------------------------------------------------------------
template<int MODE>
__global__ __launch_bounds__(256, 2) void mma_gemm(
    const float* __restrict__ A,
    const float* __restrict__ B,
    const float* __restrict__ bias,
    const float* __restrict__ rowscale,
    float* __restrict__ C,
    int lda, int ldb, int ldc, int K,
    long long sA, long long sB, long long sC,
    float alpha,
    const float* __restrict__ B1, const float* __restrict__ B2,
    const float* __restrict__ bias1, const float* __restrict__ bias2,
    float* __restrict__ C1, float* __restrict__ C2)
{
    constexpr bool BT          = (MODE == 1);
    constexpr bool CAUSAL_SKIP = (MODE == 1);
    constexpr bool CAUSAL_K    = (MODE == 2);

    const int m0 = blockIdx.y * 128;
    const int n0 = blockIdx.x * 128;
    if (CAUSAL_SKIP && n0 > m0 + 127) return;

    const int z = blockIdx.z;
    if (MODE == 0) {
        if (z == 1) { B = B1; bias = bias1; C = C1; }
        else if (z == 2) { B = B2; bias = bias2; C = C2; }
    } else {
        A += (long long)z * sA;
        B += (long long)z * sB;
        C += (long long)z * sC;
        if (MODE == 2) rowscale += (long long)z * SEQ;
    }

    const int K_end = CAUSAL_K ? (K < m0 + 128 ? K : m0 + 128) : K;
    const int n_iter = K_end >> 5;

    extern __shared__ uint32_t smem[];
    constexpr int A_WORDS = 128 * A_STRIDE;
    constexpr int B_WORDS = BT ? (128 * BT_STRIDE) : (32 * BN_STRIDE);
    uint32_t* As[2] = { smem,               smem + A_WORDS };
    uint32_t* Bs[2] = { smem + 2 * A_WORDS, smem + 2 * A_WORDS + B_WORDS };

    const int tid  = threadIdx.x;
    const int lane = tid & 31;
    const int w    = tid >> 5;
    const int wm   = w & 1;       // 0..1
    const int wn   = w >> 1;      // 0..3
    const int l4   = lane >> 2;   // 0..7
    const int lm   = lane & 3;    // 0..3

    auto load_tile = [&](int k0, int s) {
        #pragma unroll
        for (int i = 0; i < 4; i++) {
            const int idx = tid + i * 256;
            const int r   = idx >> 3;
            const int c4  = (idx & 7) << 2;
            cp16(&As[s][r * A_STRIDE + c4],
                 &A[(long long)(m0 + r) * lda + k0 + c4]);
        }
        if (BT) {
            #pragma unroll
            for (int i = 0; i < 4; i++) {
                const int idx = tid + i * 256;
                const int r   = idx >> 3;
                const int c4  = (idx & 7) << 2;
                cp16(&Bs[s][r * BT_STRIDE + c4],
                     &B[(long long)(n0 + r) * ldb + k0 + c4]);
            }
        } else {
            #pragma unroll
            for (int i = 0; i < 4; i++) {
                const int idx = tid + i * 256;
                const int kk  = idx >> 5;
                const int n4  = (idx & 31) << 2;
                cp16(&Bs[s][kk * BN_STRIDE + n4],
                     &B[(long long)(k0 + kk) * ldb + n0 + n4]);
            }
        }
    };

    float acc[4][4][4];
    #pragma unroll
    for (int i = 0; i < 4; i++)
        #pragma unroll
        for (int j = 0; j < 4; j++)
            #pragma unroll
            for (int r = 0; r < 4; r++) acc[i][j][r] = 0.0f;

    load_tile(0, 0);
    cp_commit();

    for (int it = 0; it < n_iter; it++) {
        const int s = it & 1;
        if (it + 1 < n_iter) load_tile((it + 1) << 5, s ^ 1);
        cp_commit();
        cp_wait1();
        __syncthreads();

        #pragma unroll
        for (int ks = 0; ks < 4; ks++) {
            const int kk = ks * 8;
            uint32_t a[4][4];
            uint32_t b[4][2];
            #pragma unroll
            for (int tm = 0; tm < 4; tm++) {
                const uint32_t* p = &As[s][(wm * 64 + tm * 16 + l4) * A_STRIDE + kk + lm];
                a[tm][0] = p[0];
                a[tm][1] = p[8 * A_STRIDE];
                a[tm][2] = p[4];
                a[tm][3] = p[8 * A_STRIDE + 4];
            }
            #pragma unroll
            for (int tn = 0; tn < 4; tn++) {
                if (BT) {
                    const uint32_t* p = &Bs[s][(wn * 32 + tn * 8 + l4) * BT_STRIDE + kk + lm];
                    b[tn][0] = p[0];
                    b[tn][1] = p[4];
                } else {
                    const uint32_t* p = &Bs[s][(kk + lm) * BN_STRIDE + wn * 32 + tn * 8 + l4];
                    b[tn][0] = p[0];
                    b[tn][1] = p[4 * BN_STRIDE];
                }
            }
            #pragma unroll
            for (int tm = 0; tm < 4; tm++)
                #pragma unroll
                for (int tn = 0; tn < 4; tn++) {
                    asm volatile(
                        "mma.sync.aligned.m16n8k8.row.col.f32.tf32.tf32.f32 "
                        "{%0,%1,%2,%3}, {%4,%5,%6,%7}, {%8,%9}, {%0,%1,%2,%3};\n"
                        : "+f"(acc[tm][tn][0]), "+f"(acc[tm][tn][1]),
                          "+f"(acc[tm][tn][2]), "+f"(acc[tm][tn][3])
                        : "r"(a[tm][0]), "r"(a[tm][1]), "r"(a[tm][2]), "r"(a[tm][3]),
                          "r"(b[tn][0]), "r"(b[tn][1]));
                }
        }
        __syncthreads();
    }

    // ---- epilogue ----
    #pragma unroll
    for (int tm = 0; tm < 4; tm++) {
        const int row = m0 + wm * 64 + tm * 16 + l4;
        float f0 = alpha, f1 = alpha;
        if (MODE == 2) { f0 = alpha * rowscale[row]; f1 = alpha * rowscale[row + 8]; }
        #pragma unroll
        for (int tn = 0; tn < 4; tn++) {
            const int col = n0 + wn * 32 + tn * 8 + (lm << 1);
            float bx = 0.0f, by = 0.0f;
            if (MODE == 0) { bx = bias[col]; by = bias[col + 1]; }
            float2 v0, v1;
            v0.x = acc[tm][tn][0] * f0 + bx;
            v0.y = acc[tm][tn][1] * f0 + by;
            v1.x = acc[tm][tn][2] * f1 + bx;
            v1.y = acc[tm][tn][3] * f1 + by;
            *(float2*)&C[(long long)row * ldc + col]       = v0;
            *(float2*)&C[(long long)(row + 8) * ldc + col] = v1;
        }
    }
}

// ---------------------------------------------------------------------------
// Row softmax (unnormalized): p[i] = exp(p[i]-max); g_rsum[row] = 1/sum.
// Zeros only the diagonal band tail [q+1, ceil128(q+1)) that PV's clamped
// K-loop touches. Normalization folded into the PV epilogue.
// ---------------------------------------------------------------------------
__global__ __launch_bounds__(256) void softmax_kernel(float* __restrict__ logits,
                                                      float* __restrict__ rsum)
{
    const long long row = blockIdx.x;               // 0 .. BATCH*SEQ-1
    const int q = (int)(row % SEQ);
    float* p = logits + row * SEQ;
    const int len = q + 1;
    const int band = ((q >> 7) + 1) << 7;
    const int tid = threadIdx.x;

    __shared__ float red[256];

    float mx = -INFINITY;
    for (int i = tid; i < len; i += 256) mx = fmaxf(mx, p[i]);
    red[tid] = mx;
    __syncthreads();
    for (int s = 128; s > 0; s >>= 1) {
        if (tid < s) red[tid] = fmaxf(red[tid], red[tid + s]);
        __syncthreads();
    }
    mx = red[0];
    __syncthreads();

    float sum = 0.0f;
    for (int i = tid; i < len; i += 256) {
        float e = expf(p[i] - mx);
        p[i] = e;
        sum += e;
    }
    red[tid] = sum;
    __syncthreads();
    for (int s = 128; s > 0; s >>= 1) {
        if (tid < s) red[tid] += red[tid + s];
        __syncthreads();
    }
    if (tid == 0) rsum[row] = 1.0f / red[0];

    for (int i = len + tid; i < band; i += 256) p[i] = 0.0f;
}

// ---------------------------------------------------------------------------
__global__ __launch_bounds__(256) void copy_x_kernel(const float4* __restrict__ x,
                                                     float4* __restrict__ out)
{
    const long long i = (long long)blockIdx.x * blockDim.x + threadIdx.x;
    const long long total = (long long)BATCH * SEQ * (FEAT / 4);
    if (i >= total) return;
    const long long row = i / (FEAT / 4);
    const int col = (int)(i % (FEAT / 4));
    out[row * (OUTD / 4) + col] = x[i];
}

// ---------------------------------------------------------------------------
extern "C" void kernel_launch(void* const* d_in, const int* in_sizes, int n_in,
                              void* d_out, int out_size)
{
    const float* x  = (const float*)d_in[0];
    const float* Wq = (const float*)d_in[1];
    const float* bq = (const float*)d_in[2];
    const float* Wk = (const float*)d_in[3];
    const float* bk = (const float*)d_in[4];
    const float* Wv = (const float*)d_in[5];
    const float* bv = (const float*)d_in[6];
    float* out = (float*)d_out;

    float *q, *k, *v, *logits, *rsum;
    cudaGetSymbolAddress((void**)&q,      g_q);
    cudaGetSymbolAddress((void**)&k,      g_k);
    cudaGetSymbolAddress((void**)&v,      g_v);
    cudaGetSymbolAddress((void**)&logits, g_logits);
    cudaGetSymbolAddress((void**)&rsum,   g_rsum);

    const float scale = 0.044194173824159216f;  // 1/sqrt(512)

    constexpr int SM_NN = (2 * 128 * A_STRIDE + 2 * 32 * BN_STRIDE) * 4;   // 75776 B
    constexpr int SM_NT = (2 * 128 * A_STRIDE + 2 * 128 * BT_STRIDE) * 4;  // 81920 B
    cudaFuncSetAttribute(mma_gemm<0>, cudaFuncAttributeMaxDynamicSharedMemorySize, SM_NN);
    cudaFuncSetAttribute(mma_gemm<1>, cudaFuncAttributeMaxDynamicSharedMemorySize, SM_NT);
    cudaFuncSetAttribute(mma_gemm<2>, cudaFuncAttributeMaxDynamicSharedMemorySize, SM_NN);

    // Fused QKV projections: one launch, z selects W/b/C
    {
        dim3 grid(KD / 128, (BATCH * SEQ) / 128, 3);
        mma_gemm<0><<<grid, 256, SM_NN>>>(
            x, Wq, bq, nullptr, q,
            FEAT, KD, KD, FEAT, 0, 0, 0, 1.0f,
            Wk, Wv, bk, bv, k, v);
    }

    // logits = scale * Q @ K^T  (NT, causal tile skip), batched over 8
    {
        dim3 grid(SEQ / 128, SEQ / 128, BATCH);
        mma_gemm<1><<<grid, 256, SM_NT>>>(
            q, k, nullptr, nullptr, logits,
            KD, KD, SEQ, KD,
            (long long)SEQ * KD, (long long)SEQ * KD, (long long)SEQ * SEQ, scale,
            nullptr, nullptr, nullptr, nullptr, nullptr, nullptr);
    }

    // softmax rows (unnormalized, band-zeroed; 1/sum saved for PV)
    softmax_kernel<<<BATCH * SEQ, 256>>>(logits, rsum);

    // read = (P @ V) * rowscale, into out[..., FEAT:], K clamped to band
    {
        dim3 grid(VD / 128, SEQ / 128, BATCH);
        mma_gemm<2><<<grid, 256, SM_NN>>>(
            logits, v, nullptr, rsum, out + FEAT,
            SEQ, VD, OUTD, SEQ,
            (long long)SEQ * SEQ, (long long)SEQ * VD, (long long)SEQ * OUTD, 1.0f,
            nullptr, nullptr, nullptr, nullptr, nullptr, nullptr);
    }

    // out[..., 0:FEAT] = x
    {
        const long long total = (long long)BATCH * SEQ * (FEAT / 4);
        const int grid = (int)((total + 255) / 256);
        copy_x_kernel<<<grid, 256>>>((const float4*)x, (float4*)out);
    }
}

// round 5
// speedup vs baseline: 3.6357x; 1.0017x over previous
#include <cuda_runtime.h>
#include <math.h>
#include <stdint.h>

// Problem constants
#define BATCH 8
#define SEQ   2048
#define FEAT  1024
#define KD    512
#define VD    512
#define OUTD  1536   // FEAT + VD

// Scratch (device globals; no allocations allowed)
__device__ float g_q[BATCH * SEQ * KD];
__device__ float g_k[BATCH * SEQ * KD];
__device__ float g_v[BATCH * SEQ * VD];
__device__ float g_logits[BATCH * SEQ * SEQ];   // probs, unnormalized
__device__ float g_rsum[BATCH * SEQ];           // 1/rowsum for PV epilogue

#define A_STRIDE  40   // words; conflict-free frag loads, 16B-multiple pitch
#define BT_STRIDE 40
#define BN_STRIDE 136

__device__ __forceinline__ void cp16(uint32_t* dst, const void* src) {
    uint32_t a = (uint32_t)__cvta_generic_to_shared(dst);
    asm volatile("cp.async.cg.shared.global [%0], [%1], 16;\n" :: "r"(a), "l"(src));
}
__device__ __forceinline__ void cp_commit() {
    asm volatile("cp.async.commit_group;\n" ::: "memory");
}
__device__ __forceinline__ void cp_wait1() {
    asm volatile("cp.async.wait_group 1;\n" ::: "memory");
}

// ---------------------------------------------------------------------------
// Tensor-core GEMM (mma m16n8k8 tf32, raw fp32 bits = RZ truncation)
// CTA tile 128x128, BK=32, 2-stage cp.async pipeline, 2 CTAs/SM.
// MODE 0: fused QKV projection. NN. blockIdx.z in {0,1,2} selects (B,bias,C).
// MODE 1: QK^T. NT. 1D triangular grid: blockIdx.x = tile index in lower tri.
// MODE 2: PV.  NN, causal K clamp, heavy-tiles-first, rowscale epilogue.
// ---------------------------------------------------------------------------
template<int MODE>
__global__ __launch_bounds__(256, 2) void mma_gemm(
    const float* __restrict__ A,
    const float* __restrict__ B,
    const float* __restrict__ bias,
    const float* __restrict__ rowscale,
    float* __restrict__ C,
    int lda, int ldb, int ldc, int K,
    long long sA, long long sB, long long sC,
    float alpha,
    const float* __restrict__ B1, const float* __restrict__ B2,
    const float* __restrict__ bias1, const float* __restrict__ bias2,
    float* __restrict__ C1, float* __restrict__ C2)
{
    constexpr bool BT       = (MODE == 1);
    constexpr bool CAUSAL_K = (MODE == 2);

    int m0, n0;
    if (MODE == 1) {
        // triangular decode: tile t -> (i, j), j <= i, over 16x16 tile grid
        const int t = blockIdx.x;
        int i = (int)((sqrtf(8.0f * (float)t + 1.0f) - 1.0f) * 0.5f);
        if ((i + 1) * (i + 2) / 2 <= t) i++;
        if (i * (i + 1) / 2 > t) i--;
        const int j = t - i * (i + 1) / 2;
        m0 = i * 128;
        n0 = j * 128;
    } else if (MODE == 2) {
        m0 = (gridDim.y - 1 - blockIdx.y) * 128;   // heavy tiles first
        n0 = blockIdx.x * 128;
    } else {
        m0 = blockIdx.y * 128;
        n0 = blockIdx.x * 128;
    }

    const int z = blockIdx.z;
    if (MODE == 0) {
        if (z == 1) { B = B1; bias = bias1; C = C1; }
        else if (z == 2) { B = B2; bias = bias2; C = C2; }
    } else {
        A += (long long)z * sA;
        B += (long long)z * sB;
        C += (long long)z * sC;
        if (MODE == 2) rowscale += (long long)z * SEQ;
    }

    const int K_end = CAUSAL_K ? (K < m0 + 128 ? K : m0 + 128) : K;
    const int n_iter = K_end >> 5;

    extern __shared__ uint32_t smem[];
    constexpr int A_WORDS = 128 * A_STRIDE;
    constexpr int B_WORDS = BT ? (128 * BT_STRIDE) : (32 * BN_STRIDE);
    uint32_t* As[2] = { smem,               smem + A_WORDS };
    uint32_t* Bs[2] = { smem + 2 * A_WORDS, smem + 2 * A_WORDS + B_WORDS };

    const int tid  = threadIdx.x;
    const int lane = tid & 31;
    const int w    = tid >> 5;
    const int wm   = w & 1;       // 0..1
    const int wn   = w >> 1;      // 0..3
    const int l4   = lane >> 2;   // 0..7
    const int lm   = lane & 3;    // 0..3

    auto load_tile = [&](int k0, int s) {
        #pragma unroll
        for (int i = 0; i < 4; i++) {
            const int idx = tid + i * 256;
            const int r   = idx >> 3;
            const int c4  = (idx & 7) << 2;
            cp16(&As[s][r * A_STRIDE + c4],
                 &A[(long long)(m0 + r) * lda + k0 + c4]);
        }
        if (BT) {
            #pragma unroll
            for (int i = 0; i < 4; i++) {
                const int idx = tid + i * 256;
                const int r   = idx >> 3;
                const int c4  = (idx & 7) << 2;
                cp16(&Bs[s][r * BT_STRIDE + c4],
                     &B[(long long)(n0 + r) * ldb + k0 + c4]);
            }
        } else {
            #pragma unroll
            for (int i = 0; i < 4; i++) {
                const int idx = tid + i * 256;
                const int kk  = idx >> 5;
                const int n4  = (idx & 31) << 2;
                cp16(&Bs[s][kk * BN_STRIDE + n4],
                     &B[(long long)(k0 + kk) * ldb + n0 + n4]);
            }
        }
    };

    float acc[4][4][4];
    #pragma unroll
    for (int i = 0; i < 4; i++)
        #pragma unroll
        for (int j = 0; j < 4; j++)
            #pragma unroll
            for (int r = 0; r < 4; r++) acc[i][j][r] = 0.0f;

    load_tile(0, 0);
    cp_commit();

    for (int it = 0; it < n_iter; it++) {
        const int s = it & 1;
        if (it + 1 < n_iter) load_tile((it + 1) << 5, s ^ 1);
        cp_commit();
        cp_wait1();
        __syncthreads();

        #pragma unroll
        for (int ks = 0; ks < 4; ks++) {
            const int kk = ks * 8;
            uint32_t a[4][4];
            uint32_t b[4][2];
            #pragma unroll
            for (int tm = 0; tm < 4; tm++) {
                const uint32_t* p = &As[s][(wm * 64 + tm * 16 + l4) * A_STRIDE + kk + lm];
                a[tm][0] = p[0];
                a[tm][1] = p[8 * A_STRIDE];
                a[tm][2] = p[4];
                a[tm][3] = p[8 * A_STRIDE + 4];
            }
            #pragma unroll
            for (int tn = 0; tn < 4; tn++) {
                if (BT) {
                    const uint32_t* p = &Bs[s][(wn * 32 + tn * 8 + l4) * BT_STRIDE + kk + lm];
                    b[tn][0] = p[0];
                    b[tn][1] = p[4];
                } else {
                    const uint32_t* p = &Bs[s][(kk + lm) * BN_STRIDE + wn * 32 + tn * 8 + l4];
                    b[tn][0] = p[0];
                    b[tn][1] = p[4 * BN_STRIDE];
                }
            }
            #pragma unroll
            for (int tm = 0; tm < 4; tm++)
                #pragma unroll
                for (int tn = 0; tn < 4; tn++) {
                    asm volatile(
                        "mma.sync.aligned.m16n8k8.row.col.f32.tf32.tf32.f32 "
                        "{%0,%1,%2,%3}, {%4,%5,%6,%7}, {%8,%9}, {%0,%1,%2,%3};\n"
                        : "+f"(acc[tm][tn][0]), "+f"(acc[tm][tn][1]),
                          "+f"(acc[tm][tn][2]), "+f"(acc[tm][tn][3])
                        : "r"(a[tm][0]), "r"(a[tm][1]), "r"(a[tm][2]), "r"(a[tm][3]),
                          "r"(b[tn][0]), "r"(b[tn][1]));
                }
        }
        __syncthreads();
    }

    // ---- epilogue ----
    #pragma unroll
    for (int tm = 0; tm < 4; tm++) {
        const int row = m0 + wm * 64 + tm * 16 + l4;
        float f0 = alpha, f1 = alpha;
        if (MODE == 2) { f0 = alpha * rowscale[row]; f1 = alpha * rowscale[row + 8]; }
        #pragma unroll
        for (int tn = 0; tn < 4; tn++) {
            const int col = n0 + wn * 32 + tn * 8 + (lm << 1);
            float bx = 0.0f, by = 0.0f;
            if (MODE == 0) { bx = bias[col]; by = bias[col + 1]; }
            float2 v0, v1;
            v0.x = acc[tm][tn][0] * f0 + bx;
            v0.y = acc[tm][tn][1] * f0 + by;
            v1.x = acc[tm][tn][2] * f1 + bx;
            v1.y = acc[tm][tn][3] * f1 + by;
            *(float2*)&C[(long long)row * ldc + col]       = v0;
            *(float2*)&C[(long long)(row + 8) * ldc + col] = v1;
        }
    }
}

// ---------------------------------------------------------------------------
// Warp-per-row softmax (unnormalized): p[i]=exp(p[i]-max); rsum=1/sum.
// float4 + __expf + shfl reductions, no shared memory, no __syncthreads.
// Zeros the band tail [q+1, ceil128(q+1)) that PV's clamped K-loop touches.
// ---------------------------------------------------------------------------
__global__ __launch_bounds__(256) void softmax_kernel(float* __restrict__ logits,
                                                      float* __restrict__ rsum)
{
    const int wid  = threadIdx.x >> 5;
    const int lane = threadIdx.x & 31;
    const long long row = (long long)blockIdx.x * 8 + wid;  // 8 warps/block
    const int q = (int)(row % SEQ);
    float* p = logits + row * SEQ;
    const int len  = q + 1;
    const int len4 = len >> 2;
    const int band = ((q >> 7) + 1) << 7;
    float4* p4 = (float4*)p;

    // ---- max ----
    float mx = -INFINITY;
    for (int i = lane; i < len4; i += 32) {
        float4 v = p4[i];
        mx = fmaxf(mx, fmaxf(fmaxf(v.x, v.y), fmaxf(v.z, v.w)));
    }
    for (int i = (len4 << 2) + lane; i < len; i += 32) mx = fmaxf(mx, p[i]);
    #pragma unroll
    for (int o = 16; o > 0; o >>= 1)
        mx = fmaxf(mx, __shfl_xor_sync(0xffffffffu, mx, o));

    // ---- exp + sum ----
    float sum = 0.0f;
    for (int i = lane; i < len4; i += 32) {
        float4 v = p4[i];
        v.x = __expf(v.x - mx);
        v.y = __expf(v.y - mx);
        v.z = __expf(v.z - mx);
        v.w = __expf(v.w - mx);
        p4[i] = v;
        sum += (v.x + v.y) + (v.z + v.w);
    }
    for (int i = (len4 << 2) + lane; i < len; i += 32) {
        float e = __expf(p[i] - mx);
        p[i] = e;
        sum += e;
    }
    #pragma unroll
    for (int o = 16; o > 0; o >>= 1)
        sum += __shfl_xor_sync(0xffffffffu, sum, o);

    if (lane == 0) rsum[row] = 1.0f / sum;

    // ---- zero band tail ----
    for (int i = len + lane; i < band; i += 32) p[i] = 0.0f;
}

// ---------------------------------------------------------------------------
__global__ __launch_bounds__(256) void copy_x_kernel(const float4* __restrict__ x,
                                                     float4* __restrict__ out)
{
    const long long i = (long long)blockIdx.x * blockDim.x + threadIdx.x;
    const long long total = (long long)BATCH * SEQ * (FEAT / 4);
    if (i >= total) return;
    const long long row = i / (FEAT / 4);
    const int col = (int)(i % (FEAT / 4));
    out[row * (OUTD / 4) + col] = x[i];
}

// ---------------------------------------------------------------------------
extern "C" void kernel_launch(void* const* d_in, const int* in_sizes, int n_in,
                              void* d_out, int out_size)
{
    const float* x  = (const float*)d_in[0];
    const float* Wq = (const float*)d_in[1];
    const float* bq = (const float*)d_in[2];
    const float* Wk = (const float*)d_in[3];
    const float* bk = (const float*)d_in[4];
    const float* Wv = (const float*)d_in[5];
    const float* bv = (const float*)d_in[6];
    float* out = (float*)d_out;

    float *q, *k, *v, *logits, *rsum;
    cudaGetSymbolAddress((void**)&q,      g_q);
    cudaGetSymbolAddress((void**)&k,      g_k);
    cudaGetSymbolAddress((void**)&v,      g_v);
    cudaGetSymbolAddress((void**)&logits, g_logits);
    cudaGetSymbolAddress((void**)&rsum,   g_rsum);

    const float scale = 0.044194173824159216f;  // 1/sqrt(512)

    constexpr int SM_NN = (2 * 128 * A_STRIDE + 2 * 32 * BN_STRIDE) * 4;   // 75776 B
    constexpr int SM_NT = (2 * 128 * A_STRIDE + 2 * 128 * BT_STRIDE) * 4;  // 81920 B
    cudaFuncSetAttribute(mma_gemm<0>, cudaFuncAttributeMaxDynamicSharedMemorySize, SM_NN);
    cudaFuncSetAttribute(mma_gemm<1>, cudaFuncAttributeMaxDynamicSharedMemorySize, SM_NT);
    cudaFuncSetAttribute(mma_gemm<2>, cudaFuncAttributeMaxDynamicSharedMemorySize, SM_NN);

    // Fused QKV projections: one launch, z selects W/b/C
    {
        dim3 grid(KD / 128, (BATCH * SEQ) / 128, 3);
        mma_gemm<0><<<grid, 256, SM_NN>>>(
            x, Wq, bq, nullptr, q,
            FEAT, KD, KD, FEAT, 0, 0, 0, 1.0f,
            Wk, Wv, bk, bv, k, v);
    }

    // logits = scale * Q @ K^T : triangular grid, 136 tiles/batch
    {
        dim3 grid(136, 1, BATCH);
        mma_gemm<1><<<grid, 256, SM_NT>>>(
            q, k, nullptr, nullptr, logits,
            KD, KD, SEQ, KD,
            (long long)SEQ * KD, (long long)SEQ * KD, (long long)SEQ * SEQ, scale,
            nullptr, nullptr, nullptr, nullptr, nullptr, nullptr);
    }

    // softmax: warp per row, 8 warps/block
    softmax_kernel<<<(BATCH * SEQ) / 8, 256>>>(logits, rsum);

    // read = (P @ V) * rowscale, into out[..., FEAT:], K clamped, heavy-first
    {
        dim3 grid(VD / 128, SEQ / 128, BATCH);
        mma_gemm<2><<<grid, 256, SM_NN>>>(
            logits, v, nullptr, rsum, out + FEAT,
            SEQ, VD, OUTD, SEQ,
            (long long)SEQ * SEQ, (long long)SEQ * VD, (long long)SEQ * OUTD, 1.0f,
            nullptr, nullptr, nullptr, nullptr, nullptr, nullptr);
    }

    // out[..., 0:FEAT] = x
    {
        const long long total = (long long)BATCH * SEQ * (FEAT / 4);
        const int grid = (int)((total + 255) / 256);
        copy_x_kernel<<<grid, 256>>>((const float4*)x, (float4*)out);
    }
}

// round 6
// speedup vs baseline: 4.8418x; 1.3317x over previous
#include <cuda_runtime.h>
#include <math.h>
#include <stdint.h>

// Problem constants
#define BATCH 8
#define SEQ   2048
#define FEAT  1024
#define KD    512
#define VD    512
#define OUTD  1536   // FEAT + VD

// Scratch (device globals; no allocations allowed)
__device__ float g_q[BATCH * SEQ * KD];
__device__ float g_k[BATCH * SEQ * KD];
__device__ float g_v[BATCH * SEQ * VD];
__device__ float g_logits[BATCH * SEQ * SEQ];   // probs, unnormalized
__device__ float g_rsum[BATCH * SEQ];           // 1/rowsum for PV epilogue

// 3-stage smem: per stage, A = 128x32 words (16KB) + B = 4096 words (16KB)
#define STAGE_WORDS 8192
#define SMEM_BYTES  (3 * STAGE_WORDS * 4)       // 96 KB

__device__ __forceinline__ void cp16(uint32_t* dst, const void* src) {
    uint32_t a = (uint32_t)__cvta_generic_to_shared(dst);
    asm volatile("cp.async.cg.shared.global [%0], [%1], 16;\n" :: "r"(a), "l"(src));
}
__device__ __forceinline__ void cp_commit() {
    asm volatile("cp.async.commit_group;\n" ::: "memory");
}
__device__ __forceinline__ void cp_wait1() {
    asm volatile("cp.async.wait_group 1;\n" ::: "memory");
}

// ---------------------------------------------------------------------------
// Tensor-core GEMM (mma m16n8k8 tf32, raw fp32 bits = RZ truncation)
// CTA tile 128x128, BK=32, 3-stage cp.async pipeline, XOR-swizzled smem,
// one __syncthreads per k-iteration, 2 CTAs/SM.
// MODE 0: fused QKV projection. NN. blockIdx.z in {0,1,2} selects (B,bias,C).
// MODE 1: QK^T. NT. 1D triangular grid (136 lower-tri tiles).
// MODE 2: PV.  NN, causal K clamp, rowscale epilogue.
// ---------------------------------------------------------------------------
template<int MODE>
__global__ __launch_bounds__(256, 2) void mma_gemm(
    const float* __restrict__ A,
    const float* __restrict__ B,
    const float* __restrict__ bias,
    const float* __restrict__ rowscale,
    float* __restrict__ C,
    int lda, int ldb, int ldc, int K,
    long long sA, long long sB, long long sC,
    float alpha,
    const float* __restrict__ B1, const float* __restrict__ B2,
    const float* __restrict__ bias1, const float* __restrict__ bias2,
    float* __restrict__ C1, float* __restrict__ C2)
{
    constexpr bool BT       = (MODE == 1);
    constexpr bool CAUSAL_K = (MODE == 2);

    int m0, n0;
    if (MODE == 1) {
        const int t = blockIdx.x;
        int i = (int)((sqrtf(8.0f * (float)t + 1.0f) - 1.0f) * 0.5f);
        if ((i + 1) * (i + 2) / 2 <= t) i++;
        if (i * (i + 1) / 2 > t) i--;
        const int j = t - i * (i + 1) / 2;
        m0 = i * 128;
        n0 = j * 128;
    } else {
        m0 = blockIdx.y * 128;
        n0 = blockIdx.x * 128;
    }

    const int z = blockIdx.z;
    if (MODE == 0) {
        if (z == 1) { B = B1; bias = bias1; C = C1; }
        else if (z == 2) { B = B2; bias = bias2; C = C2; }
    } else {
        A += (long long)z * sA;
        B += (long long)z * sB;
        C += (long long)z * sC;
        if (MODE == 2) rowscale += (long long)z * SEQ;
    }

    const int K_end = CAUSAL_K ? (K < m0 + 128 ? K : m0 + 128) : K;
    const int n_iter = K_end >> 5;

    extern __shared__ uint32_t smem[];

    const int tid  = threadIdx.x;
    const int lane = tid & 31;
    const int w    = tid >> 5;
    const int wm   = w & 1;       // 0..1
    const int wn   = w >> 1;      // 0..3
    const int l4   = lane >> 2;   // 0..7
    const int lm   = lane & 3;    // 0..3

    // XOR-swizzled staging:
    //   A / B-NT: word (r,c) -> r*32 + (c ^ ((r&7)<<2))
    //   B-NN:     word (k,n) -> k*128 + (n ^ ((k&3)<<3))
    auto load_tile = [&](int k0, int s) {
        uint32_t* Sa = smem + s * STAGE_WORDS;
        uint32_t* Sb = Sa + 4096;
        #pragma unroll
        for (int i = 0; i < 4; i++) {
            const int idx = tid + i * 256;
            const int r   = idx >> 3;
            const int c4  = (idx & 7) << 2;
            cp16(&Sa[r * 32 + (c4 ^ ((r & 7) << 2))],
                 &A[(long long)(m0 + r) * lda + k0 + c4]);
        }
        if (BT) {
            #pragma unroll
            for (int i = 0; i < 4; i++) {
                const int idx = tid + i * 256;
                const int r   = idx >> 3;
                const int c4  = (idx & 7) << 2;
                cp16(&Sb[r * 32 + (c4 ^ ((r & 7) << 2))],
                     &B[(long long)(n0 + r) * ldb + k0 + c4]);
            }
        } else {
            #pragma unroll
            for (int i = 0; i < 4; i++) {
                const int idx = tid + i * 256;
                const int kk  = idx >> 5;
                const int n4  = (idx & 31) << 2;
                cp16(&Sb[kk * 128 + (n4 ^ ((kk & 3) << 3))],
                     &B[(long long)(k0 + kk) * ldb + n0 + n4]);
            }
        }
    };

    float acc[4][4][4];
    #pragma unroll
    for (int i = 0; i < 4; i++)
        #pragma unroll
        for (int j = 0; j < 4; j++)
            #pragma unroll
            for (int r = 0; r < 4; r++) acc[i][j][r] = 0.0f;

    // prologue: stages 0 and 1 in flight
    load_tile(0, 0);
    cp_commit();
    if (1 < n_iter) load_tile(32, 1);
    cp_commit();

    int s = 0;        // compute stage
    int ls = 2;       // next load stage
    for (int it = 0; it < n_iter; it++) {
        cp_wait1();           // group `it` complete (committed 2 iters ago)
        __syncthreads();      // WAR: everyone done with buffer (it-1)%3

        if (it + 2 < n_iter) load_tile((it + 2) << 5, ls);
        cp_commit();          // keep group numbering iteration-aligned

        const uint32_t* Sa = smem + s * STAGE_WORDS;
        const uint32_t* Sb = Sa + 4096;

        #pragma unroll
        for (int ks = 0; ks < 4; ks++) {
            const int kk = ks * 8;
            uint32_t a[4][4];
            uint32_t b[4][2];
            #pragma unroll
            for (int tm = 0; tm < 4; tm++) {
                const int r0 = wm * 64 + tm * 16 + l4;
                const int c0 = (kk + lm) ^ (l4 << 2);
                const int c1 = (kk + lm + 4) ^ (l4 << 2);
                a[tm][0] = Sa[r0 * 32 + c0];
                a[tm][1] = Sa[(r0 + 8) * 32 + c0];
                a[tm][2] = Sa[r0 * 32 + c1];
                a[tm][3] = Sa[(r0 + 8) * 32 + c1];
            }
            #pragma unroll
            for (int tn = 0; tn < 4; tn++) {
                if (BT) {
                    const int rb = wn * 32 + tn * 8 + l4;
                    b[tn][0] = Sb[rb * 32 + ((kk + lm) ^ (l4 << 2))];
                    b[tn][1] = Sb[rb * 32 + ((kk + lm + 4) ^ (l4 << 2))];
                } else {
                    const int col = (wn * 32 + tn * 8 + l4) ^ (lm << 3);
                    b[tn][0] = Sb[(kk + lm) * 128 + col];
                    b[tn][1] = Sb[(kk + lm + 4) * 128 + col];
                }
            }
            #pragma unroll
            for (int tm = 0; tm < 4; tm++)
                #pragma unroll
                for (int tn = 0; tn < 4; tn++) {
                    asm volatile(
                        "mma.sync.aligned.m16n8k8.row.col.f32.tf32.tf32.f32 "
                        "{%0,%1,%2,%3}, {%4,%5,%6,%7}, {%8,%9}, {%0,%1,%2,%3};\n"
                        : "+f"(acc[tm][tn][0]), "+f"(acc[tm][tn][1]),
                          "+f"(acc[tm][tn][2]), "+f"(acc[tm][tn][3])
                        : "r"(a[tm][0]), "r"(a[tm][1]), "r"(a[tm][2]), "r"(a[tm][3]),
                          "r"(b[tn][0]), "r"(b[tn][1]));
                }
        }
        s  = (s  == 2) ? 0 : s + 1;
        ls = (ls == 2) ? 0 : ls + 1;
    }

    // ---- epilogue ----
    #pragma unroll
    for (int tm = 0; tm < 4; tm++) {
        const int row = m0 + wm * 64 + tm * 16 + l4;
        float f0 = alpha, f1 = alpha;
        if (MODE == 2) { f0 = alpha * rowscale[row]; f1 = alpha * rowscale[row + 8]; }
        #pragma unroll
        for (int tn = 0; tn < 4; tn++) {
            const int col = n0 + wn * 32 + tn * 8 + (lm << 1);
            float bx = 0.0f, by = 0.0f;
            if (MODE == 0) { bx = bias[col]; by = bias[col + 1]; }
            float2 v0, v1;
            v0.x = acc[tm][tn][0] * f0 + bx;
            v0.y = acc[tm][tn][1] * f0 + by;
            v1.x = acc[tm][tn][2] * f1 + bx;
            v1.y = acc[tm][tn][3] * f1 + by;
            *(float2*)&C[(long long)row * ldc + col]       = v0;
            *(float2*)&C[(long long)(row + 8) * ldc + col] = v1;
        }
    }
}

// ---------------------------------------------------------------------------
// Warp-per-row softmax (unnormalized): p[i]=exp(p[i]-max); rsum=1/sum.
// Zeros the band tail [q+1, ceil128(q+1)) that PV's clamped K-loop touches.
// ---------------------------------------------------------------------------
__global__ __launch_bounds__(256) void softmax_kernel(float* __restrict__ logits,
                                                      float* __restrict__ rsum)
{
    const int wid  = threadIdx.x >> 5;
    const int lane = threadIdx.x & 31;
    const long long row = (long long)blockIdx.x * 8 + wid;
    const int q = (int)(row % SEQ);
    float* p = logits + row * SEQ;
    const int len  = q + 1;
    const int len4 = len >> 2;
    const int band = ((q >> 7) + 1) << 7;
    float4* p4 = (float4*)p;

    float mx = -INFINITY;
    for (int i = lane; i < len4; i += 32) {
        float4 v = p4[i];
        mx = fmaxf(mx, fmaxf(fmaxf(v.x, v.y), fmaxf(v.z, v.w)));
    }
    for (int i = (len4 << 2) + lane; i < len; i += 32) mx = fmaxf(mx, p[i]);
    #pragma unroll
    for (int o = 16; o > 0; o >>= 1)
        mx = fmaxf(mx, __shfl_xor_sync(0xffffffffu, mx, o));

    float sum = 0.0f;
    for (int i = lane; i < len4; i += 32) {
        float4 v = p4[i];
        v.x = __expf(v.x - mx);
        v.y = __expf(v.y - mx);
        v.z = __expf(v.z - mx);
        v.w = __expf(v.w - mx);
        p4[i] = v;
        sum += (v.x + v.y) + (v.z + v.w);
    }
    for (int i = (len4 << 2) + lane; i < len; i += 32) {
        float e = __expf(p[i] - mx);
        p[i] = e;
        sum += e;
    }
    #pragma unroll
    for (int o = 16; o > 0; o >>= 1)
        sum += __shfl_xor_sync(0xffffffffu, sum, o);

    if (lane == 0) rsum[row] = 1.0f / sum;

    for (int i = len + lane; i < band; i += 32) p[i] = 0.0f;
}

// ---------------------------------------------------------------------------
__global__ __launch_bounds__(256) void copy_x_kernel(const float4* __restrict__ x,
                                                     float4* __restrict__ out)
{
    const long long i = (long long)blockIdx.x * blockDim.x + threadIdx.x;
    const long long total = (long long)BATCH * SEQ * (FEAT / 4);
    if (i >= total) return;
    const long long row = i / (FEAT / 4);
    const int col = (int)(i % (FEAT / 4));
    out[row * (OUTD / 4) + col] = x[i];
}

// ---------------------------------------------------------------------------
extern "C" void kernel_launch(void* const* d_in, const int* in_sizes, int n_in,
                              void* d_out, int out_size)
{
    const float* x  = (const float*)d_in[0];
    const float* Wq = (const float*)d_in[1];
    const float* bq = (const float*)d_in[2];
    const float* Wk = (const float*)d_in[3];
    const float* bk = (const float*)d_in[4];
    const float* Wv = (const float*)d_in[5];
    const float* bv = (const float*)d_in[6];
    float* out = (float*)d_out;

    float *q, *k, *v, *logits, *rsum;
    cudaGetSymbolAddress((void**)&q,      g_q);
    cudaGetSymbolAddress((void**)&k,      g_k);
    cudaGetSymbolAddress((void**)&v,      g_v);
    cudaGetSymbolAddress((void**)&logits, g_logits);
    cudaGetSymbolAddress((void**)&rsum,   g_rsum);

    const float scale = 0.044194173824159216f;  // 1/sqrt(512)

    cudaFuncSetAttribute(mma_gemm<0>, cudaFuncAttributeMaxDynamicSharedMemorySize, SMEM_BYTES);
    cudaFuncSetAttribute(mma_gemm<1>, cudaFuncAttributeMaxDynamicSharedMemorySize, SMEM_BYTES);
    cudaFuncSetAttribute(mma_gemm<2>, cudaFuncAttributeMaxDynamicSharedMemorySize, SMEM_BYTES);

    // Fused QKV projections: one launch, z selects W/b/C
    {
        dim3 grid(KD / 128, (BATCH * SEQ) / 128, 3);
        mma_gemm<0><<<grid, 256, SMEM_BYTES>>>(
            x, Wq, bq, nullptr, q,
            FEAT, KD, KD, FEAT, 0, 0, 0, 1.0f,
            Wk, Wv, bk, bv, k, v);
    }

    // logits = scale * Q @ K^T : triangular grid, 136 tiles/batch
    {
        dim3 grid(136, 1, BATCH);
        mma_gemm<1><<<grid, 256, SMEM_BYTES>>>(
            q, k, nullptr, nullptr, logits,
            KD, KD, SEQ, KD,
            (long long)SEQ * KD, (long long)SEQ * KD, (long long)SEQ * SEQ, scale,
            nullptr, nullptr, nullptr, nullptr, nullptr, nullptr);
    }

    // softmax: warp per row, 8 warps/block
    softmax_kernel<<<(BATCH * SEQ) / 8, 256>>>(logits, rsum);

    // read = (P @ V) * rowscale, into out[..., FEAT:], K clamped to band
    {
        dim3 grid(VD / 128, SEQ / 128, BATCH);
        mma_gemm<2><<<grid, 256, SMEM_BYTES>>>(
            logits, v, nullptr, rsum, out + FEAT,
            SEQ, VD, OUTD, SEQ,
            (long long)SEQ * SEQ, (long long)SEQ * VD, (long long)SEQ * OUTD, 1.0f,
            nullptr, nullptr, nullptr, nullptr, nullptr, nullptr);
    }

    // out[..., 0:FEAT] = x
    {
        const long long total = (long long)BATCH * SEQ * (FEAT / 4);
        const int grid = (int)((total + 255) / 256);
        copy_x_kernel<<<grid, 256>>>((const float4*)x, (float4*)out);
    }
}